// round 1
// baseline (speedup 1.0000x reference)
#include <cuda_runtime.h>
#include <cstdint>

// WindowAttention fused kernel (Swin-style), sm_103a.
// B=8192 windows, N=49 tokens, C=128, H=4 heads, HD=32.
// One CTA per window, 256 threads (8 warps). All GEMMs via mma.sync tf32.
// Pipeline (all in SMEM): x -> qkv -> scores -> softmax(+bias+mask) -> O -> proj -> gmem.

#define NTOK 49
#define MPAD 64          // padded token dim for 16-row mma tiles
#define CDIM 128
#define NH   4
#define HDIM 32
#define LD   132         // row stride (floats) for x/q/k/v/out tiles
#define LDSC 60          // row stride (floats) for score tiles (56 cols used)

// SMEM layout (floats):
//   qs  [64][132]  @ 0      (reused as O buffer in phase 4/5)
//   ks  [64][132]  @ 8448
//   vs  [64][132]  @ 16896
//   sx  region     @ 25344  size 15360  (x tile in phase 1; scores[4][64][60] after)
//   rel [2401] int @ 40704  (pad to 2404)
//   tbl [169*4]    @ 43108
#define OFF_Q   0
#define OFF_K   8448
#define OFF_V   16896
#define OFF_SX  25344
#define OFF_REL 40704
#define OFF_TBL 43108
#define SMEM_FLOATS 43784

__device__ __forceinline__ uint32_t f2tf(float f) {
    uint32_t u;
    asm("cvt.rna.tf32.f32 %0, %1;" : "=r"(u) : "f"(f));
    return u;
}

__device__ __forceinline__ void mma8(float* d, const uint32_t* a, const uint32_t* b) {
    asm volatile(
        "mma.sync.aligned.m16n8k8.row.col.f32.tf32.tf32.f32 "
        "{%0,%1,%2,%3},{%4,%5,%6,%7},{%8,%9},{%0,%1,%2,%3};"
        : "+f"(d[0]), "+f"(d[1]), "+f"(d[2]), "+f"(d[3])
        : "r"(a[0]), "r"(a[1]), "r"(a[2]), "r"(a[3]),
          "r"(b[0]), "r"(b[1]));
}

__global__ __launch_bounds__(256, 1)
void winattn_kernel(const float* __restrict__ x,
                    const float* __restrict__ mask,
                    const float* __restrict__ qkv_w,
                    const float* __restrict__ qkv_b,
                    const float* __restrict__ rel_tbl,
                    const float* __restrict__ proj_w,
                    const float* __restrict__ proj_b,
                    const int*   __restrict__ rel_idx,
                    float*       __restrict__ out)
{
    extern __shared__ float sm[];
    float* qs  = sm + OFF_Q;
    float* ks  = sm + OFF_K;
    float* vs  = sm + OFF_V;
    float* sx  = sm + OFF_SX;                 // x tile, later scores
    int*   rls = (int*)(sm + OFF_REL);
    float* tbl = sm + OFF_TBL;

    const int tid  = threadIdx.x;
    const int lane = tid & 31;
    const int warp = tid >> 5;
    const int g    = lane >> 2;   // groupID (0..7)
    const int tg   = lane & 3;    // threadID_in_group (0..3)
    const int b    = blockIdx.x;

    // ---- Phase 0: stage x window, rel index and bias table ----
    for (int i = tid; i < 2401; i += 256) rls[i] = rel_idx[i];
    for (int i = tid; i < 169 * NH; i += 256) tbl[i] = rel_tbl[i];
    {
        const float* xg = x + (size_t)b * NTOK * CDIM;
        for (int i = tid; i < MPAD * CDIM; i += 256) {
            int r = i >> 7, c = i & 127;
            sx[r * LD + c] = (r < NTOK) ? xg[r * CDIM + c] : 0.0f;
        }
    }
    __syncthreads();

    // ---- Phase 1: qkv = x @ qkv_w + b  (M=64, K=128, N=384) ----
    // warp owns 48 output columns: [warp*48, warp*48+48)
    {
        float acc[4][6][4];
        #pragma unroll
        for (int mt = 0; mt < 4; mt++)
            #pragma unroll
            for (int nt = 0; nt < 6; nt++)
                #pragma unroll
                for (int e = 0; e < 4; e++) acc[mt][nt][e] = 0.0f;

        for (int kk = 0; kk < CDIM; kk += 8) {
            uint32_t Bf[6][2];
            #pragma unroll
            for (int nt = 0; nt < 6; nt++) {
                int col = warp * 48 + nt * 8 + g;
                Bf[nt][0] = f2tf(qkv_w[(kk + tg) * 384 + col]);
                Bf[nt][1] = f2tf(qkv_w[(kk + tg + 4) * 384 + col]);
            }
            #pragma unroll
            for (int mt = 0; mt < 4; mt++) {
                uint32_t Af[4];
                int r = mt * 16 + g;
                Af[0] = f2tf(sx[r * LD + kk + tg]);
                Af[1] = f2tf(sx[(r + 8) * LD + kk + tg]);
                Af[2] = f2tf(sx[r * LD + kk + tg + 4]);
                Af[3] = f2tf(sx[(r + 8) * LD + kk + tg + 4]);
                #pragma unroll
                for (int nt = 0; nt < 6; nt++) mma8(acc[mt][nt], Af, Bf[nt]);
            }
        }

        const float scale = 0.17677669529663687f;  // 32^-0.5
        #pragma unroll
        for (int mt = 0; mt < 4; mt++)
            #pragma unroll
            for (int nt = 0; nt < 6; nt++)
                #pragma unroll
                for (int e = 0; e < 4; e++) {
                    int row = mt * 16 + g + ((e >= 2) ? 8 : 0);
                    int col = warp * 48 + nt * 8 + 2 * tg + (e & 1);
                    float v = acc[mt][nt][e] + qkv_b[col];
                    if (col < 128)       qs[row * LD + col] = v * scale;
                    else if (col < 256)  ks[row * LD + (col - 128)] = v;
                    else                 vs[row * LD + (col - 256)] = v;
                }
    }
    __syncthreads();

    // ---- Phase 2: scores S_h = q_h @ k_h^T  (per head M=64, N=56, K=32) ----
    // warp -> head = warp/2, m-half = warp%2 (m-tiles {2*mh, 2*mh+1})
    {
        const int h  = warp >> 1;
        const int mh = warp & 1;
        float sacc[2][7][4];
        #pragma unroll
        for (int mi = 0; mi < 2; mi++)
            #pragma unroll
            for (int nt = 0; nt < 7; nt++)
                #pragma unroll
                for (int e = 0; e < 4; e++) sacc[mi][nt][e] = 0.0f;

        #pragma unroll
        for (int kk = 0; kk < HDIM; kk += 8) {
            int kb = h * HDIM + kk;
            uint32_t Bf[7][2];
            #pragma unroll
            for (int nt = 0; nt < 7; nt++) {
                int key = nt * 8 + g;
                Bf[nt][0] = f2tf(ks[key * LD + kb + tg]);
                Bf[nt][1] = f2tf(ks[key * LD + kb + tg + 4]);
            }
            #pragma unroll
            for (int mi = 0; mi < 2; mi++) {
                uint32_t Af[4];
                int r = (mh * 2 + mi) * 16 + g;
                Af[0] = f2tf(qs[r * LD + kb + tg]);
                Af[1] = f2tf(qs[(r + 8) * LD + kb + tg]);
                Af[2] = f2tf(qs[r * LD + kb + tg + 4]);
                Af[3] = f2tf(qs[(r + 8) * LD + kb + tg + 4]);
                #pragma unroll
                for (int nt = 0; nt < 7; nt++) mma8(sacc[mi][nt], Af, Bf[nt]);
            }
        }

        float* sh = sx + h * MPAD * LDSC;
        #pragma unroll
        for (int mi = 0; mi < 2; mi++)
            #pragma unroll
            for (int nt = 0; nt < 7; nt++)
                #pragma unroll
                for (int e = 0; e < 4; e++) {
                    int row = (mh * 2 + mi) * 16 + g + ((e >= 2) ? 8 : 0);
                    int col = nt * 8 + 2 * tg + (e & 1);
                    sh[row * LDSC + col] = sacc[mi][nt][e];
                }
    }
    __syncthreads();

    // ---- Phase 3: softmax(S + rel_bias + mask) along keys, per (head,row) ----
    if (tid < NH * NTOK) {
        const int h   = tid / NTOK;
        const int row = tid % NTOK;
        float* srow = sx + h * MPAD * LDSC + row * LDSC;
        const float* mrow = mask + ((size_t)b * NTOK + row) * NTOK;
        const int* rrow = rls + row * NTOK;

        float mx = -1e30f;
        for (int j = 0; j < NTOK; j++) {
            float v = srow[j] + tbl[rrow[j] * NH + h] + mrow[j];
            srow[j] = v;
            mx = fmaxf(mx, v);
        }
        float sum = 0.0f;
        for (int j = 0; j < NTOK; j++) {
            float e = expf(srow[j] - mx);
            srow[j] = e;
            sum += e;
        }
        float inv = 1.0f / sum;
        for (int j = 0; j < NTOK; j++) srow[j] *= inv;
        // zero padded key columns (49..55) so the P@V GEMM ignores them
        for (int j = NTOK; j < 56; j++) srow[j] = 0.0f;
    }
    __syncthreads();

    // ---- Phase 4: O_h = P_h @ v_h  (per head M=64, N=32, K=56) -> qs buffer ----
    {
        const int h  = warp >> 1;
        const int mh = warp & 1;
        float* sh = sx + h * MPAD * LDSC;
        float oacc[2][4][4];
        #pragma unroll
        for (int mi = 0; mi < 2; mi++)
            #pragma unroll
            for (int nt = 0; nt < 4; nt++)
                #pragma unroll
                for (int e = 0; e < 4; e++) oacc[mi][nt][e] = 0.0f;

        #pragma unroll
        for (int kk = 0; kk < 56; kk += 8) {
            uint32_t Bf[4][2];
            #pragma unroll
            for (int nt = 0; nt < 4; nt++) {
                int vc = h * HDIM + nt * 8 + g;
                Bf[nt][0] = f2tf(vs[(kk + tg) * LD + vc]);
                Bf[nt][1] = f2tf(vs[(kk + tg + 4) * LD + vc]);
            }
            #pragma unroll
            for (int mi = 0; mi < 2; mi++) {
                uint32_t Af[4];
                int r = (mh * 2 + mi) * 16 + g;
                Af[0] = f2tf(sh[r * LDSC + kk + tg]);
                Af[1] = f2tf(sh[(r + 8) * LDSC + kk + tg]);
                Af[2] = f2tf(sh[r * LDSC + kk + tg + 4]);
                Af[3] = f2tf(sh[(r + 8) * LDSC + kk + tg + 4]);
                #pragma unroll
                for (int nt = 0; nt < 4; nt++) mma8(oacc[mi][nt], Af, Bf[nt]);
            }
        }

        // store O into qs (q is dead after phase 2; syncthreads above fence it)
        #pragma unroll
        for (int mi = 0; mi < 2; mi++)
            #pragma unroll
            for (int nt = 0; nt < 4; nt++)
                #pragma unroll
                for (int e = 0; e < 4; e++) {
                    int row = (mh * 2 + mi) * 16 + g + ((e >= 2) ? 8 : 0);
                    int col = h * HDIM + nt * 8 + 2 * tg + (e & 1);
                    qs[row * LD + col] = oacc[mi][nt][e];
                }
    }
    __syncthreads();

    // ---- Phase 5: result = O @ proj_w + proj_b  (M=64, K=128, N=128) ----
    // warp owns 16 output columns
    {
        float pacc[4][2][4];
        #pragma unroll
        for (int mt = 0; mt < 4; mt++)
            #pragma unroll
            for (int nt = 0; nt < 2; nt++)
                #pragma unroll
                for (int e = 0; e < 4; e++) pacc[mt][nt][e] = 0.0f;

        for (int kk = 0; kk < CDIM; kk += 8) {
            uint32_t Bf[2][2];
            #pragma unroll
            for (int nt = 0; nt < 2; nt++) {
                int col = warp * 16 + nt * 8 + g;
                Bf[nt][0] = f2tf(proj_w[(kk + tg) * CDIM + col]);
                Bf[nt][1] = f2tf(proj_w[(kk + tg + 4) * CDIM + col]);
            }
            #pragma unroll
            for (int mt = 0; mt < 4; mt++) {
                uint32_t Af[4];
                int r = mt * 16 + g;
                Af[0] = f2tf(qs[r * LD + kk + tg]);
                Af[1] = f2tf(qs[(r + 8) * LD + kk + tg]);
                Af[2] = f2tf(qs[r * LD + kk + tg + 4]);
                Af[3] = f2tf(qs[(r + 8) * LD + kk + tg + 4]);
                #pragma unroll
                for (int nt = 0; nt < 2; nt++) mma8(pacc[mt][nt], Af, Bf[nt]);
            }
        }

        float* og = out + (size_t)b * NTOK * CDIM;
        #pragma unroll
        for (int mt = 0; mt < 4; mt++)
            #pragma unroll
            for (int nt = 0; nt < 2; nt++)
                #pragma unroll
                for (int e = 0; e < 4; e++) {
                    int row = mt * 16 + g + ((e >= 2) ? 8 : 0);
                    int col = warp * 16 + nt * 8 + 2 * tg + (e & 1);
                    if (row < NTOK)
                        og[row * CDIM + col] = pacc[mt][nt][e] + proj_b[col];
                }
    }
}

extern "C" void kernel_launch(void* const* d_in, const int* in_sizes, int n_in,
                              void* d_out, int out_size) {
    const float* x      = (const float*)d_in[0];
    const float* mask   = (const float*)d_in[1];
    const float* qkv_w  = (const float*)d_in[2];
    const float* qkv_b  = (const float*)d_in[3];
    const float* rtbl   = (const float*)d_in[4];
    const float* proj_w = (const float*)d_in[5];
    const float* proj_b = (const float*)d_in[6];
    const int*   ridx   = (const int*)d_in[7];
    float* out = (float*)d_out;

    const int B = in_sizes[0] / (NTOK * CDIM);
    const int smem_bytes = SMEM_FLOATS * sizeof(float);
    cudaFuncSetAttribute(winattn_kernel,
                         cudaFuncAttributeMaxDynamicSharedMemorySize, smem_bytes);
    winattn_kernel<<<B, 256, smem_bytes>>>(x, mask, qkv_w, qkv_b, rtbl,
                                           proj_w, proj_b, ridx, out);
}